// round 11
// baseline (speedup 1.0000x reference)
#include <cuda_runtime.h>
#include <cuda_fp16.h>
#include <cuda_bf16.h>
#include <math.h>

// Problem constants
#define BATCH 32
#define CIN   128
#define CB16  (CIN/16)
#define HH    64
#define WW    64
#define HW    (HH*WW)
#define EMB   384
#define ECB   (EMB/16)     // 24
#define EB    128
#define HID   24

// ---------------- scratch (device globals) ----------------------------------
__device__ float  g_fused[(size_t)BATCH * EMB * HW];
__device__ float  g_gout [(size_t)BATCH * EMB * HW];
__device__ float  g_avg  [BATCH * EMB];
__device__ float  g_max  [BATCH * EMB];
__device__ float  g_attn [BATCH * EMB];
__device__ __half g_xh   [(size_t)BATCH * CB16 * HW * 16];  // [b][cb][h][w][c16]
__device__ __half g_fh   [(size_t)BATCH * ECB * HW * 16];   // fused*attn fp16
__device__ __half g_wh3  [9  * EB * CIN];                   // [tap][oc][c]
__device__ __half g_wh5  [25 * EB * CIN];
__device__ __half g_wh7  [49 * EB * CIN];
__device__ __half g_wfh  [EMB * EMB];                       // fusion weights fp16 [o][c]

// ---- helpers ---------------------------------------------------------------
__device__ __forceinline__ void mma_f16(float& d0, float& d1, float& d2, float& d3,
                                        unsigned a0, unsigned a1, unsigned a2, unsigned a3,
                                        unsigned b0, unsigned b1) {
    asm("mma.sync.aligned.m16n8k16.row.col.f32.f16.f16.f32 "
        "{%0,%1,%2,%3}, {%4,%5,%6,%7}, {%8,%9}, {%0,%1,%2,%3};"
        : "+f"(d0), "+f"(d1), "+f"(d2), "+f"(d3)
        : "r"(a0), "r"(a1), "r"(a2), "r"(a3), "r"(b0), "r"(b1));
}
__device__ __forceinline__ void ldsm_x4(unsigned& r0, unsigned& r1, unsigned& r2, unsigned& r3,
                                        unsigned addr) {
    asm volatile("ldmatrix.sync.aligned.m8n8.x4.shared.b16 {%0,%1,%2,%3}, [%4];"
                 : "=r"(r0), "=r"(r1), "=r"(r2), "=r"(r3) : "r"(addr));
}
__device__ __forceinline__ void cpa16(unsigned dst, const void* src, unsigned srcbytes) {
    asm volatile("cp.async.cg.shared.global [%0], [%1], 16, %2;"
                 :: "r"(dst), "l"(src), "r"(srcbytes) : "memory");
}
__device__ __forceinline__ void cpa_commit() {
    asm volatile("cp.async.commit_group;" ::: "memory");
}
template<int N>
__device__ __forceinline__ void cpa_wait() {
    asm volatile("cp.async.wait_group %0;" :: "n"(N) : "memory");
}

// ---------------------------------------------------------------------------
// Pre-pass: x [B][C][H][W] fp32 -> g_xh [b][cb][h][w][c16] fp16
// ---------------------------------------------------------------------------
__global__ __launch_bounds__(256)
void prep_xh_kernel(const float* __restrict__ x, __half* __restrict__ xh)
{
    __shared__ __half s[16][129];
    const int hw0 = blockIdx.x * 128;
    const int cb  = blockIdx.y;
    const int b   = blockIdx.z;
    const int t   = threadIdx.x;

#pragma unroll
    for (int p = 0; p < 8; ++p) {
        int ci = p * 2 + (t >> 7);
        int j  = t & 127;
        s[ci][j] = __float2half(x[((size_t)(b * CIN + cb * 16 + ci)) * HW + hw0 + j]);
    }
    __syncthreads();

    int j    = t >> 1;
    int csel = t & 1;
    __half tmp[8];
#pragma unroll
    for (int k = 0; k < 8; ++k) tmp[k] = s[csel * 8 + k][j];
    *reinterpret_cast<uint4*>(&xh[(((size_t)(b * CB16 + cb)) * HW + hw0 + j) * 16 + csel * 8]) =
        *reinterpret_cast<uint4*>(tmp);
}

// Pre-pass: fused*attn fp32 -> g_fh [b][cb][hw][c16] fp16
__global__ __launch_bounds__(256)
void prep_fh_kernel(const float* __restrict__ fused, const float* __restrict__ attn,
                    __half* __restrict__ fh)
{
    __shared__ __half s[16][129];
    const int hw0 = blockIdx.x * 128;
    const int cb  = blockIdx.y;
    const int b   = blockIdx.z;
    const int t   = threadIdx.x;

#pragma unroll
    for (int p = 0; p < 8; ++p) {
        int ci = p * 2 + (t >> 7);
        int j  = t & 127;
        int c  = cb * 16 + ci;
        s[ci][j] = __float2half(fused[((size_t)(b * EMB + c)) * HW + hw0 + j] *
                                attn[b * EMB + c]);
    }
    __syncthreads();

    int j    = t >> 1;
    int csel = t & 1;
    __half tmp[8];
#pragma unroll
    for (int k = 0; k < 8; ++k) tmp[k] = s[csel * 8 + k][j];
    *reinterpret_cast<uint4*>(&fh[(((size_t)(b * ECB + cb)) * HW + hw0 + j) * 16 + csel * 8]) =
        *reinterpret_cast<uint4*>(tmp);
}

// Pre-pass: w [oc][c][kk] fp32 -> wh [kk][oc][c] fp16
__global__ __launch_bounds__(256)
void prep_wh_kernel(const float* __restrict__ w, __half* __restrict__ wh, int kkN)
{
    int idx = blockIdx.x * 256 + threadIdx.x;
    int total = kkN * EB * CIN;
    if (idx < total) {
        int c  = idx & 127;
        int oc = (idx >> 7) & 127;
        int kk = idx >> 14;
        wh[idx] = __float2half(w[((size_t)oc * CIN + c) * kkN + kk]);
    }
}

// Pre-pass: fusion weights fp32 -> fp16
__global__ __launch_bounds__(256)
void prep_wfh_kernel(const float* __restrict__ w, __half* __restrict__ wh)
{
    int idx = blockIdx.x * 256 + threadIdx.x;
    if (idx < EMB * EMB) wh[idx] = __float2half(w[idx]);
}

// ---------------------------------------------------------------------------
// Conv body (templated device function): fp16 mma + ldmatrix + cp.async
// pipeline.  Called from the unified conv kernel below.
// ---------------------------------------------------------------------------
template<int K, int ROWS, int OCB>
__device__ __forceinline__
void conv_body(const __half* __restrict__ xh, const __half* __restrict__ wh,
               const float* __restrict__ bias, float* __restrict__ out, int ch_off,
               int h0, int b, int ocbase, unsigned char* dsm)
{
    constexpr int HALO    = K / 2;
    constexpr int WIN     = WW + K - 1;
    constexpr int IN_ROWS = ROWS + K - 1;
    constexpr int NOG     = OCB / 32;
    constexpr int NSG     = 8 / NOG;       // == ROWS
    constexpr int NITEM   = K * OCB;
    constexpr int WCH     = NITEM * 2;
    constexpr int NWPF    = (WCH + 255) / 256;
    constexpr int NCHUNK  = IN_ROWS * WIN * 2;
    constexpr int SINB    = IN_ROWS * WIN * 32;
    constexpr int SWB     = K * OCB * 32;
    constexpr int S       = CB16 * K;

    const unsigned base = (unsigned)__cvta_generic_to_shared(dsm);
    const unsigned sin_base[2] = { base, base + SINB };
    const unsigned sw_base [3] = { base + 2 * SINB,
                                   base + 2 * SINB + SWB,
                                   base + 2 * SINB + 2 * SWB };

    const int t      = threadIdx.x;
    const int warp   = t >> 5;
    const int lane   = t & 31;
    const int gid    = lane >> 2;
    const int tig    = lane & 3;
    const int ocg    = warp / NSG;
    const int rw     = warp % NSG;

    float d[2][8][4];
#pragma unroll
    for (int mm = 0; mm < 2; ++mm)
#pragma unroll
        for (int n = 0; n < 8; ++n)
#pragma unroll
            for (int j = 0; j < 4; ++j) d[mm][n][j] = 0.f;

    const int laneA  = lane & 15;
    const int cselA  = (lane >> 4) & 1;
    const int laneB4 = (lane & 7) | (((lane >> 4) & 1) << 3);
    const int cselB4 = (lane >> 3) & 1;

    const __half* xbase = xh + ((size_t)(b * CB16)) * HW * 16;

    auto issue_w = [&](int s2) {
        if (s2 >= S) return;
        const int cb2 = s2 / K;
        const int g2  = s2 - cb2 * K;
        const unsigned dstb = sw_base[s2 % 3];
#pragma unroll
        for (int j = 0; j < NWPF; ++j) {
            int q = t + j * 256;
            if (q < WCH) {
                int it = q >> 1, half = q & 1;
                int tap = it / OCB, oc = it - tap * OCB;
                const __half* src = wh + ((size_t)(g2 * K + tap) * EB + ocbase + oc) * CIN
                                       + cb2 * 16 + half * 8;
                unsigned off = (unsigned)(it * 32 + half * 16) ^ ((it & 4) << 2);
                cpa16(dstb + off, src, 16);
            }
        }
    };
    auto issue_in = [&](int cb) {
        const __half* xc = xbase + (size_t)cb * HW * 16;
        const unsigned dstb = sin_base[cb & 1];
        for (int q = t; q < NCHUNK; q += 256) {
            int n = q >> 1, cs = q & 1;
            int r = n / WIN, col = n - r * WIN;
            int gr = h0 + r - HALO, gw = col - HALO;
            bool inb = ((unsigned)gr < HH) && ((unsigned)gw < WW);
            const __half* src = inb ? (xc + ((size_t)gr * WW + gw) * 16 + cs * 8) : xc;
            unsigned off = (unsigned)(n * 32 + cs * 16) ^ ((n & 4) << 2);
            cpa16(dstb + off, src, inb ? 16u : 0u);
        }
    };

    issue_w(0); issue_in(0); cpa_commit();
    issue_w(1); cpa_commit();

    for (int s = 0; s < S; ++s) {
        const int cb = s / K;
        const int g  = s - cb * K;

        cpa_wait<1>();
        __syncthreads();

        issue_w(s + 2);
        if (g == K - 2 && cb + 1 < CB16) issue_in(cb + 1);
        cpa_commit();

        const unsigned swb  = sw_base[s % 3];
        const unsigned sinb = sin_base[cb & 1];
        const int rowbase = (rw + g) * WIN;
#pragma unroll
        for (int kw = 0; kw < K; ++kw) {
            unsigned a[2][4];
#pragma unroll
            for (int mm = 0; mm < 2; ++mm) {
                int gA = kw * OCB + ocg * 32 + mm * 16 + laneA;
                unsigned offA = (unsigned)(gA * 32 + cselA * 16) ^ ((gA & 4) << 2);
                ldsm_x4(a[mm][0], a[mm][1], a[mm][2], a[mm][3], swb + offA);
            }
#pragma unroll
            for (int ntp = 0; ntp < 4; ++ntp) {
                int gB = rowbase + ntp * 16 + laneB4 + kw;
                unsigned offB = (unsigned)(gB * 32 + cselB4 * 16) ^ ((gB & 4) << 2);
                unsigned b0, b1, b2, b3;
                ldsm_x4(b0, b1, b2, b3, sinb + offB);
                const int n0 = ntp * 2;
                mma_f16(d[0][n0][0], d[0][n0][1], d[0][n0][2], d[0][n0][3],
                        a[0][0], a[0][1], a[0][2], a[0][3], b0, b1);
                mma_f16(d[1][n0][0], d[1][n0][1], d[1][n0][2], d[1][n0][3],
                        a[1][0], a[1][1], a[1][2], a[1][3], b0, b1);
                mma_f16(d[0][n0+1][0], d[0][n0+1][1], d[0][n0+1][2], d[0][n0+1][3],
                        a[0][0], a[0][1], a[0][2], a[0][3], b2, b3);
                mma_f16(d[1][n0+1][0], d[1][n0+1][1], d[1][n0+1][2], d[1][n0+1][3],
                        a[1][0], a[1][1], a[1][2], a[1][3], b2, b3);
            }
        }
    }

    const int h = h0 + rw;
#pragma unroll
    for (int mm = 0; mm < 2; ++mm) {
        int oc0 = ocbase + ocg * 32 + mm * 16 + gid;
        float bv0 = bias[oc0];
        float bv1 = bias[oc0 + 8];
#pragma unroll
        for (int n = 0; n < 8; ++n) {
            int w0 = n * 8 + tig * 2;
            float* p0 = out + (((size_t)b * EMB + ch_off + oc0) * HH + h) * WW + w0;
            float* p1 = p0 + (size_t)8 * HW;
            *reinterpret_cast<float2*>(p0) = make_float2(d[mm][n][0] + bv0, d[mm][n][1] + bv0);
            *reinterpret_cast<float2*>(p1) = make_float2(d[mm][n][2] + bv1, d[mm][n][3] + bv1);
        }
    }
}

// ---------------------------------------------------------------------------
// Unified conv kernel: 3072 blocks, bid%3 interleaves K7/K5/K3 so every wave
// mixes long and short blocks (no per-kernel tails, better balancing).
// ---------------------------------------------------------------------------
__global__ __launch_bounds__(256, 2)
void conv_all_kernel(const __half* __restrict__ xh,
                     const __half* __restrict__ wh3, const __half* __restrict__ wh5,
                     const __half* __restrict__ wh7,
                     const float* __restrict__ b3, const float* __restrict__ b5,
                     const float* __restrict__ b7,
                     float* __restrict__ out)
{
    extern __shared__ __align__(128) unsigned char dsm[];
    const int bid = blockIdx.x;
    const int sel = bid % 3;
    const int sub = bid / 3;

    if (sel == 0) {
        // K7: ROWS=4, OCB=64 -> 16 h-blocks x 32 b x 2 oc-halves
        int h0 = (sub & 15) * 4;
        int b  = (sub >> 4) & 31;
        int oc = (sub >> 9) * 64;
        conv_body<7, 4, 64>(xh, wh7, b7, out, 2 * EB, h0, b, oc, dsm);
    } else if (sel == 1) {
        // K5: ROWS=2, OCB=128 -> 32 h-blocks x 32 b
        int h0 = (sub & 31) * 2;
        int b  = sub >> 5;
        conv_body<5, 2, 128>(xh, wh5, b5, out, EB, h0, b, 0, dsm);
    } else {
        // K3: ROWS=2, OCB=128
        int h0 = (sub & 31) * 2;
        int b  = sub >> 5;
        conv_body<3, 2, 128>(xh, wh3, b3, out, 0, h0, b, 0, dsm);
    }
}

// ---------------------------------------------------------------------------
// Fusion 1x1 conv as fp16 GEMM.
// ---------------------------------------------------------------------------
__global__ __launch_bounds__(256)
void gemm_f16_kernel(const __half* __restrict__ fh, const __half* __restrict__ wfh,
                     const float* __restrict__ fb, float* __restrict__ out)
{
    __shared__ __align__(128) unsigned char sA[2][4096];
    __shared__ __align__(128) unsigned char sB[2][4096];

    const int obase = blockIdx.x * 128;
    const int hw0   = blockIdx.y * 128;
    const int b     = blockIdx.z;
    const int t     = threadIdx.x;
    const int warp  = t >> 5;
    const int lane  = t & 31;
    const int gid   = lane >> 2;
    const int tig   = lane & 3;
    const int ocg   = warp >> 1;
    const int hwg   = warp & 1;

    const unsigned sAb[2] = { (unsigned)__cvta_generic_to_shared(sA[0]),
                              (unsigned)__cvta_generic_to_shared(sA[1]) };
    const unsigned sBb[2] = { (unsigned)__cvta_generic_to_shared(sB[0]),
                              (unsigned)__cvta_generic_to_shared(sB[1]) };

    const int laneA  = lane & 15;
    const int cselA  = (lane >> 4) & 1;
    const int laneB4 = (lane & 7) | (((lane >> 4) & 1) << 3);
    const int cselB4 = (lane >> 3) & 1;

    float d[2][8][4];
#pragma unroll
    for (int mm = 0; mm < 2; ++mm)
#pragma unroll
        for (int n = 0; n < 8; ++n)
#pragma unroll
            for (int j = 0; j < 4; ++j) d[mm][n][j] = 0.f;

    const int grow = t >> 1;
    const int gcs  = t & 1;
    const unsigned stoff = (unsigned)(grow * 32 + gcs * 16) ^ ((grow & 4) << 2);

    const __half* Asrc = wfh + (size_t)(obase + grow) * EMB + gcs * 8;
    const __half* Bsrc = fh + ((size_t)b * ECB * HW + hw0 + grow) * 16 + gcs * 8;

    uint4 av = *reinterpret_cast<const uint4*>(Asrc);
    uint4 bv = *reinterpret_cast<const uint4*>(Bsrc);

    for (int cb = 0; cb < ECB; ++cb) {
        const int p = cb & 1;
        *reinterpret_cast<uint4*>(sA[p] + stoff) = av;
        *reinterpret_cast<uint4*>(sB[p] + stoff) = bv;
        if (cb + 1 < ECB) {
            av = *reinterpret_cast<const uint4*>(Asrc + (cb + 1) * 16);
            bv = *reinterpret_cast<const uint4*>(Bsrc + (size_t)(cb + 1) * HW * 16);
        }
        __syncthreads();

        unsigned a[2][4];
#pragma unroll
        for (int mm = 0; mm < 2; ++mm) {
            int gA = ocg * 32 + mm * 16 + laneA;
            unsigned offA = (unsigned)(gA * 32 + cselA * 16) ^ ((gA & 4) << 2);
            ldsm_x4(a[mm][0], a[mm][1], a[mm][2], a[mm][3], sAb[p] + offA);
        }
        const int rowbase = hwg * 64;
#pragma unroll
        for (int ntp = 0; ntp < 4; ++ntp) {
            int gB = rowbase + ntp * 16 + laneB4;
            unsigned offB = (unsigned)(gB * 32 + cselB4 * 16) ^ ((gB & 4) << 2);
            unsigned b0, b1, b2, b3;
            ldsm_x4(b0, b1, b2, b3, sBb[p] + offB);
            const int n0 = ntp * 2;
            mma_f16(d[0][n0][0], d[0][n0][1], d[0][n0][2], d[0][n0][3],
                    a[0][0], a[0][1], a[0][2], a[0][3], b0, b1);
            mma_f16(d[1][n0][0], d[1][n0][1], d[1][n0][2], d[1][n0][3],
                    a[1][0], a[1][1], a[1][2], a[1][3], b0, b1);
            mma_f16(d[0][n0+1][0], d[0][n0+1][1], d[0][n0+1][2], d[0][n0+1][3],
                    a[0][0], a[0][1], a[0][2], a[0][3], b2, b3);
            mma_f16(d[1][n0+1][0], d[1][n0+1][1], d[1][n0+1][2], d[1][n0+1][3],
                    a[1][0], a[1][1], a[1][2], a[1][3], b2, b3);
        }
    }

#pragma unroll
    for (int mm = 0; mm < 2; ++mm) {
        int oc0 = obase + ocg * 32 + mm * 16 + gid;
        float bv0 = fb[oc0];
        float bv1 = fb[oc0 + 8];
#pragma unroll
        for (int n = 0; n < 8; ++n) {
            int col = hw0 + hwg * 64 + n * 8 + tig * 2;
            float* p0 = out + ((size_t)b * EMB + oc0) * HW + col;
            float* p1 = p0 + (size_t)8 * HW;
            *reinterpret_cast<float2*>(p0) = make_float2(d[mm][n][0] + bv0, d[mm][n][1] + bv0);
            *reinterpret_cast<float2*>(p1) = make_float2(d[mm][n][2] + bv1, d[mm][n][3] + bv1);
        }
    }
}

// ---------------------------------------------------------------------------
// Global avg + max pool per (b, e).
// ---------------------------------------------------------------------------
__global__ __launch_bounds__(256)
void pool_kernel(const float* __restrict__ fused,
                 float* __restrict__ avg_out, float* __restrict__ max_out)
{
    const int e = blockIdx.x;
    const int b = blockIdx.y;
    const int t = threadIdx.x;

    const float4* p = reinterpret_cast<const float4*>(fused + ((size_t)b * EMB + e) * HW);

    float s = 0.f, m = -INFINITY;
#pragma unroll
    for (int i = 0; i < 4; ++i) {
        float4 v = p[t + i * 256];
        s += v.x + v.y + v.z + v.w;
        m = fmaxf(m, fmaxf(fmaxf(v.x, v.y), fmaxf(v.z, v.w)));
    }

    __shared__ float ss[256], sm[256];
    ss[t] = s; sm[t] = m;
    __syncthreads();
    for (int o = 128; o > 0; o >>= 1) {
        if (t < o) { ss[t] += ss[t + o]; sm[t] = fmaxf(sm[t], sm[t + o]); }
        __syncthreads();
    }
    if (t == 0) {
        avg_out[b * EMB + e] = ss[0] * (1.f / (float)HW);
        max_out[b * EMB + e] = sm[0];
    }
}

// ---------------------------------------------------------------------------
// CBAM MLP + sigmoid.
// ---------------------------------------------------------------------------
__global__ __launch_bounds__(EMB)
void attn_kernel(const float* __restrict__ avg_in, const float* __restrict__ max_in,
                 const float* __restrict__ w1, const float* __restrict__ w2,
                 float* __restrict__ attn)
{
    const int b = blockIdx.x;
    const int t = threadIdx.x;

    __shared__ float s_avg[EMB], s_max[EMB];
    __shared__ float s_h[HID];
    __shared__ float s_ha[HID], s_hm[HID];

    s_avg[t] = avg_in[b * EMB + t];
    s_max[t] = max_in[b * EMB + t];
    __syncthreads();

    if (t < HID) {
        float a = 0.f;
        const float* w1r = w1 + t * EMB;
        for (int e = 0; e < EMB; ++e) a = fmaf(s_avg[e], w1r[e], a);
        s_ha[t] = fmaxf(a, 0.f);
    } else if (t >= 32 && t < 32 + HID) {
        int j = t - 32;
        float a = 0.f;
        const float* w1r = w1 + j * EMB;
        for (int e = 0; e < EMB; ++e) a = fmaf(s_max[e], w1r[e], a);
        s_hm[j] = fmaxf(a, 0.f);
    }
    __syncthreads();
    if (t < HID) s_h[t] = s_ha[t] + s_hm[t];
    __syncthreads();

    float v = 0.f;
    const float* w2r = w2 + t * HID;
#pragma unroll
    for (int j = 0; j < HID; ++j) v = fmaf(s_h[j], w2r[j], v);
    attn[b * EMB + t] = 1.f / (1.f + expf(-v));
}

// ---------------------------------------------------------------------------
// Transpose [B,E,HW] -> [B,HW,E] + LayerNorm over E.  32-token tiles
// (128B coalesced row segments), dynamic smem [384][33].
// ---------------------------------------------------------------------------
__global__ __launch_bounds__(256)
void ln_kernel(const float* __restrict__ g, const float* __restrict__ gamma,
               const float* __restrict__ beta, float* __restrict__ out)
{
    extern __shared__ float s[];   // [EMB][33]

    const int hw0 = blockIdx.x * 32;
    const int b   = blockIdx.y;
    const int t   = threadIdx.x;

    const float* gb = g + (size_t)b * EMB * HW + hw0;
    for (int i = t; i < EMB * 8; i += 256) {
        int e = i >> 3;
        int q = i & 7;
        float4 v = *reinterpret_cast<const float4*>(gb + (size_t)e * HW + q * 4);
        float* dst = &s[e * 33 + q * 4];
        dst[0] = v.x; dst[1] = v.y; dst[2] = v.z; dst[3] = v.w;
    }
    __syncthreads();

    const int warp = t >> 5;
    const int lane = t & 31;

#pragma unroll
    for (int tt = 0; tt < 4; ++tt) {
        int tok = warp * 4 + tt;
        float vals[12];
        float sum = 0.f, sq = 0.f;
#pragma unroll
        for (int k = 0; k < 12; ++k) {
            float v = s[(lane + 32 * k) * 33 + tok];
            vals[k] = v;
            sum += v;
            sq  = fmaf(v, v, sq);
        }
#pragma unroll
        for (int o = 16; o > 0; o >>= 1) {
            sum += __shfl_xor_sync(0xFFFFFFFFu, sum, o);
            sq  += __shfl_xor_sync(0xFFFFFFFFu, sq,  o);
        }
        float mu  = sum * (1.f / (float)EMB);
        float var = sq * (1.f / (float)EMB) - mu * mu;
        float rstd = rsqrtf(var + 1e-5f);

        float* dst = out + ((size_t)b * HW + hw0 + tok) * EMB;
#pragma unroll
        for (int k = 0; k < 12; ++k) {
            int e = lane + 32 * k;
            dst[e] = (vals[k] - mu) * rstd * gamma[e] + beta[e];
        }
    }
}

// ---------------------------------------------------------------------------
// Launcher.
// ---------------------------------------------------------------------------
extern "C" void kernel_launch(void* const* d_in, const int* in_sizes, int n_in,
                              void* d_out, int out_size)
{
    const float* x   = (const float*)d_in[0];
    const float* w3  = (const float*)d_in[1];
    const float* b3  = (const float*)d_in[2];
    const float* w5  = (const float*)d_in[3];
    const float* b5  = (const float*)d_in[4];
    const float* w7  = (const float*)d_in[5];
    const float* b7  = (const float*)d_in[6];
    const float* cw1 = (const float*)d_in[7];
    const float* cw2 = (const float*)d_in[8];
    const float* fw  = (const float*)d_in[9];
    const float* fbi = (const float*)d_in[10];
    const float* lng = (const float*)d_in[11];
    const float* lnb = (const float*)d_in[12];
    float* out = (float*)d_out;

    float* fused; cudaGetSymbolAddress((void**)&fused, g_fused);
    float* gout;  cudaGetSymbolAddress((void**)&gout,  g_gout);
    float* gavg;  cudaGetSymbolAddress((void**)&gavg,  g_avg);
    float* gmax;  cudaGetSymbolAddress((void**)&gmax,  g_max);
    float* gattn; cudaGetSymbolAddress((void**)&gattn, g_attn);
    __half* xh;  cudaGetSymbolAddress((void**)&xh,  g_xh);
    __half* fh;  cudaGetSymbolAddress((void**)&fh,  g_fh);
    __half* wh3; cudaGetSymbolAddress((void**)&wh3, g_wh3);
    __half* wh5; cudaGetSymbolAddress((void**)&wh5, g_wh5);
    __half* wh7; cudaGetSymbolAddress((void**)&wh7, g_wh7);
    __half* wfh; cudaGetSymbolAddress((void**)&wfh, g_wfh);

    // unified conv smem = max over K variants:
    //  K3: 2*(4*66*32)+3*(3*128*32)=53760 ; K5: 2*(6*68*32)+3*(5*128*32)=87552
    //  K7: 2*(10*70*32)+3*(7*64*32)=87808
    constexpr int SMALL = 87808;
    constexpr int LNSM  = EMB * 33 * 4;     // 50688
    cudaFuncSetAttribute(conv_all_kernel, cudaFuncAttributeMaxDynamicSharedMemorySize, SMALL);
    cudaFuncSetAttribute(ln_kernel,       cudaFuncAttributeMaxDynamicSharedMemorySize, LNSM);

    // pre-pass conversions
    prep_xh_kernel<<<dim3(HW / 128, CB16, BATCH), 256>>>(x, xh);
    prep_wh_kernel<<<(9  * EB * CIN + 255) / 256, 256>>>(w3, wh3, 9);
    prep_wh_kernel<<<(25 * EB * CIN + 255) / 256, 256>>>(w5, wh5, 25);
    prep_wh_kernel<<<(49 * EB * CIN + 255) / 256, 256>>>(w7, wh7, 49);
    prep_wfh_kernel<<<(EMB * EMB + 255) / 256, 256>>>(fw, wfh);

    // unified convs: 3072 blocks, K7/K5/K3 interleaved
    conv_all_kernel<<<3072, 256, SMALL>>>(xh, wh3, wh5, wh7, b3, b5, b7, fused);

    pool_kernel<<<dim3(EMB, BATCH), 256>>>(fused, gavg, gmax);
    attn_kernel<<<BATCH, EMB>>>(gavg, gmax, cw1, cw2, gattn);

    prep_fh_kernel<<<dim3(HW / 128, ECB, BATCH), 256>>>(fused, gattn, fh);
    gemm_f16_kernel<<<dim3(EMB / 128, HW / 128, BATCH), 256>>>(fh, wfh, fbi, gout);

    ln_kernel<<<dim3(HW / 32, BATCH), 256, LNSM>>>(gout, lng, lnb, out);
}

// round 12
// speedup vs baseline: 1.0453x; 1.0453x over previous
#include <cuda_runtime.h>
#include <cuda_fp16.h>
#include <cuda_bf16.h>
#include <math.h>

// Problem constants
#define BATCH 32
#define CIN   128
#define CB16  (CIN/16)
#define HH    64
#define WW    64
#define HW    (HH*WW)
#define EMB   384
#define ECB   (EMB/16)     // 24
#define EB    128
#define HID   24

// ---------------- scratch (device globals) ----------------------------------
__device__ float  g_gout [(size_t)BATCH * EMB * HW];
__device__ float  g_avg  [BATCH * EMB];
__device__ float  g_max  [BATCH * EMB];
__device__ float  g_attn [BATCH * EMB];
__device__ __half g_xh   [(size_t)BATCH * CB16 * HW * 16];  // [b][cb][h][w][c16]
__device__ __half g_fh   [(size_t)BATCH * ECB * HW * 16];   // conv out fp16 [b][cb][hw][c16]
__device__ __half g_wh3  [9  * EB * CIN];                   // [tap][oc][c]
__device__ __half g_wh5  [25 * EB * CIN];
__device__ __half g_wh7  [49 * EB * CIN];
__device__ __half g_wfh  [EMB * EMB];                       // fusion weights fp16 [o][c]

// ---- helpers ---------------------------------------------------------------
__device__ __forceinline__ void mma_f16(float& d0, float& d1, float& d2, float& d3,
                                        unsigned a0, unsigned a1, unsigned a2, unsigned a3,
                                        unsigned b0, unsigned b1) {
    asm("mma.sync.aligned.m16n8k16.row.col.f32.f16.f16.f32 "
        "{%0,%1,%2,%3}, {%4,%5,%6,%7}, {%8,%9}, {%0,%1,%2,%3};"
        : "+f"(d0), "+f"(d1), "+f"(d2), "+f"(d3)
        : "r"(a0), "r"(a1), "r"(a2), "r"(a3), "r"(b0), "r"(b1));
}
__device__ __forceinline__ void ldsm_x4(unsigned& r0, unsigned& r1, unsigned& r2, unsigned& r3,
                                        unsigned addr) {
    asm volatile("ldmatrix.sync.aligned.m8n8.x4.shared.b16 {%0,%1,%2,%3}, [%4];"
                 : "=r"(r0), "=r"(r1), "=r"(r2), "=r"(r3) : "r"(addr));
}
__device__ __forceinline__ void cpa16(unsigned dst, const void* src, unsigned srcbytes) {
    asm volatile("cp.async.cg.shared.global [%0], [%1], 16, %2;"
                 :: "r"(dst), "l"(src), "r"(srcbytes) : "memory");
}
__device__ __forceinline__ void cpa_commit() {
    asm volatile("cp.async.commit_group;" ::: "memory");
}
template<int N>
__device__ __forceinline__ void cpa_wait() {
    asm volatile("cp.async.wait_group %0;" :: "n"(N) : "memory");
}

// ---------------------------------------------------------------------------
// Pre-pass: x [B][C][H][W] fp32 -> g_xh [b][cb][h][w][c16] fp16
// ---------------------------------------------------------------------------
__global__ __launch_bounds__(256)
void prep_xh_kernel(const float* __restrict__ x, __half* __restrict__ xh)
{
    __shared__ __half s[16][129];
    const int hw0 = blockIdx.x * 128;
    const int cb  = blockIdx.y;
    const int b   = blockIdx.z;
    const int t   = threadIdx.x;

#pragma unroll
    for (int p = 0; p < 8; ++p) {
        int ci = p * 2 + (t >> 7);
        int j  = t & 127;
        s[ci][j] = __float2half(x[((size_t)(b * CIN + cb * 16 + ci)) * HW + hw0 + j]);
    }
    __syncthreads();

    int j    = t >> 1;
    int csel = t & 1;
    __half tmp[8];
#pragma unroll
    for (int k = 0; k < 8; ++k) tmp[k] = s[csel * 8 + k][j];
    *reinterpret_cast<uint4*>(&xh[(((size_t)(b * CB16 + cb)) * HW + hw0 + j) * 16 + csel * 8]) =
        *reinterpret_cast<uint4*>(tmp);
}

// Pre-pass: w [oc][c][kk] fp32 -> wh [kk][oc][c] fp16
__global__ __launch_bounds__(256)
void prep_wh_kernel(const float* __restrict__ w, __half* __restrict__ wh, int kkN)
{
    int idx = blockIdx.x * 256 + threadIdx.x;
    int total = kkN * EB * CIN;
    if (idx < total) {
        int c  = idx & 127;
        int oc = (idx >> 7) & 127;
        int kk = idx >> 14;
        wh[idx] = __float2half(w[((size_t)oc * CIN + c) * kkN + kk]);
    }
}

// Pre-pass: fusion weights fp32 -> fp16
__global__ __launch_bounds__(256)
void prep_wfh_kernel(const float* __restrict__ w, __half* __restrict__ wh)
{
    int idx = blockIdx.x * 256 + threadIdx.x;
    if (idx < EMB * EMB) wh[idx] = __float2half(w[idx]);
}

// ---------------------------------------------------------------------------
// Conv via fp16 mma m16n8k16 + ldmatrix + cp.async pipeline (round-8 mainloop).
// NEW epilogue: smem transpose -> fh fp16 [b][cbg][hw][c16] directly
// (g_fused fp32 and prep_fh are eliminated).
// ---------------------------------------------------------------------------
template<int K, int ROWS, int OCB>
__global__ __launch_bounds__(256, 2)
void conv_f16_kernel(const __half* __restrict__ xh, const __half* __restrict__ wh,
                     const float* __restrict__ bias, __half* __restrict__ fh, int ch_off)
{
    constexpr int HALO    = K / 2;
    constexpr int WIN     = WW + K - 1;
    constexpr int IN_ROWS = ROWS + K - 1;
    constexpr int NOG     = OCB / 32;
    constexpr int NSG     = 8 / NOG;       // == ROWS
    constexpr int NITEM   = K * OCB;
    constexpr int WCH     = NITEM * 2;
    constexpr int NWPF    = (WCH + 255) / 256;
    constexpr int NCHUNK  = IN_ROWS * WIN * 2;
    constexpr int SINB    = IN_ROWS * WIN * 32;
    constexpr int SWB     = K * OCB * 32;
    constexpr int S       = CB16 * K;

    extern __shared__ __align__(128) unsigned char dsm[];
    const unsigned base = (unsigned)__cvta_generic_to_shared(dsm);
    const unsigned sin_base[2] = { base, base + SINB };
    const unsigned sw_base [3] = { base + 2 * SINB,
                                   base + 2 * SINB + SWB,
                                   base + 2 * SINB + 2 * SWB };

    const int h0     = blockIdx.x * ROWS;
    const int b      = blockIdx.y;
    const int ocbase = blockIdx.z * OCB;
    const int t      = threadIdx.x;
    const int warp   = t >> 5;
    const int lane   = t & 31;
    const int gid    = lane >> 2;
    const int tig    = lane & 3;
    const int ocg    = warp / NSG;
    const int rw     = warp % NSG;

    float d[2][8][4];
#pragma unroll
    for (int mm = 0; mm < 2; ++mm)
#pragma unroll
        for (int n = 0; n < 8; ++n)
#pragma unroll
            for (int j = 0; j < 4; ++j) d[mm][n][j] = 0.f;

    const int laneA  = lane & 15;
    const int cselA  = (lane >> 4) & 1;
    const int laneB4 = (lane & 7) | (((lane >> 4) & 1) << 3);
    const int cselB4 = (lane >> 3) & 1;

    const __half* xbase = xh + ((size_t)(b * CB16)) * HW * 16;

    auto issue_w = [&](int s2) {
        if (s2 >= S) return;
        const int cb2 = s2 / K;
        const int g2  = s2 - cb2 * K;
        const unsigned dstb = sw_base[s2 % 3];
#pragma unroll
        for (int j = 0; j < NWPF; ++j) {
            int q = t + j * 256;
            if (q < WCH) {
                int it = q >> 1, half = q & 1;
                int tap = it / OCB, oc = it - tap * OCB;
                const __half* src = wh + ((size_t)(g2 * K + tap) * EB + ocbase + oc) * CIN
                                       + cb2 * 16 + half * 8;
                unsigned off = (unsigned)(it * 32 + half * 16) ^ ((it & 4) << 2);
                cpa16(dstb + off, src, 16);
            }
        }
    };
    auto issue_in = [&](int cb) {
        const __half* xc = xbase + (size_t)cb * HW * 16;
        const unsigned dstb = sin_base[cb & 1];
        for (int q = t; q < NCHUNK; q += 256) {
            int n = q >> 1, cs = q & 1;
            int r = n / WIN, col = n - r * WIN;
            int gr = h0 + r - HALO, gw = col - HALO;
            bool inb = ((unsigned)gr < HH) && ((unsigned)gw < WW);
            const __half* src = inb ? (xc + ((size_t)gr * WW + gw) * 16 + cs * 8) : xc;
            unsigned off = (unsigned)(n * 32 + cs * 16) ^ ((n & 4) << 2);
            cpa16(dstb + off, src, inb ? 16u : 0u);
        }
    };

    issue_w(0); issue_in(0); cpa_commit();
    issue_w(1); cpa_commit();

    for (int s = 0; s < S; ++s) {
        const int cb = s / K;
        const int g  = s - cb * K;

        cpa_wait<1>();
        __syncthreads();

        issue_w(s + 2);
        if (g == K - 2 && cb + 1 < CB16) issue_in(cb + 1);
        cpa_commit();

        const unsigned swb  = sw_base[s % 3];
        const unsigned sinb = sin_base[cb & 1];
        const int rowbase = (rw + g) * WIN;
#pragma unroll
        for (int kw = 0; kw < K; ++kw) {
            unsigned a[2][4];
#pragma unroll
            for (int mm = 0; mm < 2; ++mm) {
                int gA = kw * OCB + ocg * 32 + mm * 16 + laneA;
                unsigned offA = (unsigned)(gA * 32 + cselA * 16) ^ ((gA & 4) << 2);
                ldsm_x4(a[mm][0], a[mm][1], a[mm][2], a[mm][3], swb + offA);
            }
#pragma unroll
            for (int ntp = 0; ntp < 4; ++ntp) {
                int gB = rowbase + ntp * 16 + laneB4 + kw;
                unsigned offB = (unsigned)(gB * 32 + cselB4 * 16) ^ ((gB & 4) << 2);
                unsigned b0, b1, b2, b3;
                ldsm_x4(b0, b1, b2, b3, sinb + offB);
                const int n0 = ntp * 2;
                mma_f16(d[0][n0][0], d[0][n0][1], d[0][n0][2], d[0][n0][3],
                        a[0][0], a[0][1], a[0][2], a[0][3], b0, b1);
                mma_f16(d[1][n0][0], d[1][n0][1], d[1][n0][2], d[1][n0][3],
                        a[1][0], a[1][1], a[1][2], a[1][3], b0, b1);
                mma_f16(d[0][n0+1][0], d[0][n0+1][1], d[0][n0+1][2], d[0][n0+1][3],
                        a[0][0], a[0][1], a[0][2], a[0][3], b2, b3);
                mma_f16(d[1][n0+1][0], d[1][n0+1][1], d[1][n0+1][2], d[1][n0+1][3],
                        a[1][0], a[1][1], a[1][2], a[1][3], b2, b3);
            }
        }
    }

    // ---- epilogue: smem transpose -> fh fp16 [cbg][hw][c16] ----
    constexpr int P   = ROWS * 64 + 8;            // half stride (even)
    constexpr int NCH = (OCB / 16) * (ROWS * 64) * 2;   // 8-half chunks
    __syncthreads();   // mainloop smem reads finished
    __half* ep = reinterpret_cast<__half*>(dsm);

    const int hwb = rw * 64;
#pragma unroll
    for (int mm = 0; mm < 2; ++mm) {
        int ocl = ocg * 32 + mm * 16 + gid;
        float bv0 = bias[ocbase + ocl];
        float bv1 = bias[ocbase + ocl + 8];
#pragma unroll
        for (int n = 0; n < 8; ++n) {
            int hwl = hwb + n * 8 + tig * 2;
            *reinterpret_cast<__half2*>(&ep[ocl * P + hwl]) =
                __floats2half2_rn(d[mm][n][0] + bv0, d[mm][n][1] + bv0);
            *reinterpret_cast<__half2*>(&ep[(ocl + 8) * P + hwl]) =
                __floats2half2_rn(d[mm][n][2] + bv1, d[mm][n][3] + bv1);
        }
    }
    __syncthreads();

    const int cbg0 = (ch_off + ocbase) >> 4;
    __half* fdst = fh + ((size_t)b * ECB + cbg0) * HW * 16 + (size_t)h0 * 64 * 16;
#pragma unroll
    for (int qi = 0; qi < NCH / 256; ++qi) {
        int q   = t + qi * 256;
        int cbl = q / (ROWS * 64 * 2);
        int rem = q - cbl * (ROWS * 64 * 2);
        int hwl = rem >> 1;
        int cs  = rem & 1;
        __half tmp[8];
#pragma unroll
        for (int j = 0; j < 8; ++j)
            tmp[j] = ep[(cbl * 16 + cs * 8 + j) * P + hwl];
        *reinterpret_cast<uint4*>(&fdst[((size_t)cbl * HW + hwl) * 16 + cs * 8]) =
            *reinterpret_cast<uint4*>(tmp);
    }
}

// ---------------------------------------------------------------------------
// Pool over fh fp16 [b][cb][hw][c16]: block = (cb, b), 256 threads.
// Thread t: hw = t>>1 (stride 128), cs = t&1 (8 channels). Coalesced uint4.
// ---------------------------------------------------------------------------
__global__ __launch_bounds__(256)
void pool_kernel(const __half* __restrict__ fh,
                 float* __restrict__ avg_out, float* __restrict__ max_out)
{
    __shared__ float rs[256][8];
    __shared__ float rm[256][8];

    const int cb = blockIdx.x;
    const int b  = blockIdx.y;
    const int t  = threadIdx.x;
    const int li = t >> 1;
    const int g  = t & 1;

    const __half* src = fh + ((size_t)(b * ECB + cb)) * HW * 16;

    float s[8], m[8];
#pragma unroll
    for (int j = 0; j < 8; ++j) { s[j] = 0.f; m[j] = -INFINITY; }

    for (int it = 0; it < 32; ++it) {
        uint4 v = *reinterpret_cast<const uint4*>(src + ((size_t)(li + it * 128)) * 16 + g * 8);
        const __half2* h2 = reinterpret_cast<const __half2*>(&v);
#pragma unroll
        for (int p = 0; p < 4; ++p) {
            float2 f = __half22float2(h2[p]);
            s[2 * p]     += f.x;
            s[2 * p + 1] += f.y;
            m[2 * p]     = fmaxf(m[2 * p], f.x);
            m[2 * p + 1] = fmaxf(m[2 * p + 1], f.y);
        }
    }
#pragma unroll
    for (int j = 0; j < 8; ++j) { rs[t][j] = s[j]; rm[t][j] = m[j]; }
    __syncthreads();

    for (int o = 64; o > 0; o >>= 1) {
        if (li < o) {
#pragma unroll
            for (int j = 0; j < 8; ++j) {
                rs[t][j] += rs[t + 2 * o][j];
                rm[t][j] = fmaxf(rm[t][j], rm[t + 2 * o][j]);
            }
        }
        __syncthreads();
    }
    if (li == 0) {
#pragma unroll
        for (int j = 0; j < 8; ++j) {
            int e = cb * 16 + g * 8 + j;
            avg_out[b * EMB + e] = rs[t][j] * (1.f / (float)HW);
            max_out[b * EMB + e] = rm[t][j];
        }
    }
}

// ---------------------------------------------------------------------------
// CBAM MLP + sigmoid.
// ---------------------------------------------------------------------------
__global__ __launch_bounds__(EMB)
void attn_kernel(const float* __restrict__ avg_in, const float* __restrict__ max_in,
                 const float* __restrict__ w1, const float* __restrict__ w2,
                 float* __restrict__ attn)
{
    const int b = blockIdx.x;
    const int t = threadIdx.x;

    __shared__ float s_avg[EMB], s_max[EMB];
    __shared__ float s_h[HID];
    __shared__ float s_ha[HID], s_hm[HID];

    s_avg[t] = avg_in[b * EMB + t];
    s_max[t] = max_in[b * EMB + t];
    __syncthreads();

    if (t < HID) {
        float a = 0.f;
        const float* w1r = w1 + t * EMB;
        for (int e = 0; e < EMB; ++e) a = fmaf(s_avg[e], w1r[e], a);
        s_ha[t] = fmaxf(a, 0.f);
    } else if (t >= 32 && t < 32 + HID) {
        int j = t - 32;
        float a = 0.f;
        const float* w1r = w1 + j * EMB;
        for (int e = 0; e < EMB; ++e) a = fmaf(s_max[e], w1r[e], a);
        s_hm[j] = fmaxf(a, 0.f);
    }
    __syncthreads();
    if (t < HID) s_h[t] = s_ha[t] + s_hm[t];
    __syncthreads();

    float v = 0.f;
    const float* w2r = w2 + t * HID;
#pragma unroll
    for (int j = 0; j < HID; ++j) v = fmaf(s_h[j], w2r[j], v);
    attn[b * EMB + t] = 1.f / (1.f + expf(-v));
}

// ---------------------------------------------------------------------------
// Fusion 1x1 conv as fp16 GEMM; attn folded into A (weights) at staging.
// ---------------------------------------------------------------------------
__global__ __launch_bounds__(256)
void gemm_f16_kernel(const __half* __restrict__ fh, const __half* __restrict__ wfh,
                     const float* __restrict__ attn,
                     const float* __restrict__ fb, float* __restrict__ out)
{
    __shared__ __align__(128) unsigned char sA[2][4096];
    __shared__ __align__(128) unsigned char sB[2][4096];
    __shared__ __half2 s_attn[EMB / 2];

    const int obase = blockIdx.x * 128;
    const int hw0   = blockIdx.y * 128;
    const int b     = blockIdx.z;
    const int t     = threadIdx.x;
    const int warp  = t >> 5;
    const int lane  = t & 31;
    const int gid   = lane >> 2;
    const int tig   = lane & 3;
    const int ocg   = warp >> 1;
    const int hwg   = warp & 1;

    const unsigned sAb[2] = { (unsigned)__cvta_generic_to_shared(sA[0]),
                              (unsigned)__cvta_generic_to_shared(sA[1]) };
    const unsigned sBb[2] = { (unsigned)__cvta_generic_to_shared(sB[0]),
                              (unsigned)__cvta_generic_to_shared(sB[1]) };

    const int laneA  = lane & 15;
    const int cselA  = (lane >> 4) & 1;
    const int laneB4 = (lane & 7) | (((lane >> 4) & 1) << 3);
    const int cselB4 = (lane >> 3) & 1;

    // attn -> half2 cache
    for (int i = t; i < EMB / 2; i += 256)
        s_attn[i] = __floats2half2_rn(attn[b * EMB + 2 * i], attn[b * EMB + 2 * i + 1]);

    float d[2][8][4];
#pragma unroll
    for (int mm = 0; mm < 2; ++mm)
#pragma unroll
        for (int n = 0; n < 8; ++n)
#pragma unroll
            for (int j = 0; j < 4; ++j) d[mm][n][j] = 0.f;

    const int grow = t >> 1;
    const int gcs  = t & 1;
    const unsigned stoff = (unsigned)(grow * 32 + gcs * 16) ^ ((grow & 4) << 2);

    const __half* Asrc = wfh + (size_t)(obase + grow) * EMB + gcs * 8;
    const __half* Bsrc = fh + ((size_t)b * ECB * HW + hw0 + grow) * 16 + gcs * 8;

    uint4 av = *reinterpret_cast<const uint4*>(Asrc);
    uint4 bv = *reinterpret_cast<const uint4*>(Bsrc);

    __syncthreads();   // s_attn ready

    for (int cb = 0; cb < ECB; ++cb) {
        const int p = cb & 1;
        // scale weights by attn at store time
        {
            uint4 avm;
            const __half2* sw2 = reinterpret_cast<const __half2*>(&av);
            __half2* dw2 = reinterpret_cast<__half2*>(&avm);
            const int c2 = (cb * 16 + gcs * 8) >> 1;
#pragma unroll
            for (int pp = 0; pp < 4; ++pp)
                dw2[pp] = __hmul2(sw2[pp], s_attn[c2 + pp]);
            *reinterpret_cast<uint4*>(sA[p] + stoff) = avm;
        }
        *reinterpret_cast<uint4*>(sB[p] + stoff) = bv;
        if (cb + 1 < ECB) {
            av = *reinterpret_cast<const uint4*>(Asrc + (cb + 1) * 16);
            bv = *reinterpret_cast<const uint4*>(Bsrc + (size_t)(cb + 1) * HW * 16);
        }
        __syncthreads();

        unsigned a[2][4];
#pragma unroll
        for (int mm = 0; mm < 2; ++mm) {
            int gA = ocg * 32 + mm * 16 + laneA;
            unsigned offA = (unsigned)(gA * 32 + cselA * 16) ^ ((gA & 4) << 2);
            ldsm_x4(a[mm][0], a[mm][1], a[mm][2], a[mm][3], sAb[p] + offA);
        }
        const int rowbase = hwg * 64;
#pragma unroll
        for (int ntp = 0; ntp < 4; ++ntp) {
            int gB = rowbase + ntp * 16 + laneB4;
            unsigned offB = (unsigned)(gB * 32 + cselB4 * 16) ^ ((gB & 4) << 2);
            unsigned b0, b1, b2, b3;
            ldsm_x4(b0, b1, b2, b3, sBb[p] + offB);
            const int n0 = ntp * 2;
            mma_f16(d[0][n0][0], d[0][n0][1], d[0][n0][2], d[0][n0][3],
                    a[0][0], a[0][1], a[0][2], a[0][3], b0, b1);
            mma_f16(d[1][n0][0], d[1][n0][1], d[1][n0][2], d[1][n0][3],
                    a[1][0], a[1][1], a[1][2], a[1][3], b0, b1);
            mma_f16(d[0][n0+1][0], d[0][n0+1][1], d[0][n0+1][2], d[0][n0+1][3],
                    a[0][0], a[0][1], a[0][2], a[0][3], b2, b3);
            mma_f16(d[1][n0+1][0], d[1][n0+1][1], d[1][n0+1][2], d[1][n0+1][3],
                    a[1][0], a[1][1], a[1][2], a[1][3], b2, b3);
        }
    }

#pragma unroll
    for (int mm = 0; mm < 2; ++mm) {
        int oc0 = obase + ocg * 32 + mm * 16 + gid;
        float bv0 = fb[oc0];
        float bv1 = fb[oc0 + 8];
#pragma unroll
        for (int n = 0; n < 8; ++n) {
            int col = hw0 + hwg * 64 + n * 8 + tig * 2;
            float* p0 = out + ((size_t)b * EMB + oc0) * HW + col;
            float* p1 = p0 + (size_t)8 * HW;
            *reinterpret_cast<float2*>(p0) = make_float2(d[mm][n][0] + bv0, d[mm][n][1] + bv0);
            *reinterpret_cast<float2*>(p1) = make_float2(d[mm][n][2] + bv1, d[mm][n][3] + bv1);
        }
    }
}

// ---------------------------------------------------------------------------
// Transpose [B,E,HW] -> [B,HW,E] + LayerNorm over E.  32-token tiles.
// ---------------------------------------------------------------------------
__global__ __launch_bounds__(256)
void ln_kernel(const float* __restrict__ g, const float* __restrict__ gamma,
               const float* __restrict__ beta, float* __restrict__ out)
{
    extern __shared__ float s[];   // [EMB][33]

    const int hw0 = blockIdx.x * 32;
    const int b   = blockIdx.y;
    const int t   = threadIdx.x;

    const float* gb = g + (size_t)b * EMB * HW + hw0;
    for (int i = t; i < EMB * 8; i += 256) {
        int e = i >> 3;
        int q = i & 7;
        float4 v = *reinterpret_cast<const float4*>(gb + (size_t)e * HW + q * 4);
        float* dst = &s[e * 33 + q * 4];
        dst[0] = v.x; dst[1] = v.y; dst[2] = v.z; dst[3] = v.w;
    }
    __syncthreads();

    const int warp = t >> 5;
    const int lane = t & 31;

#pragma unroll
    for (int tt = 0; tt < 4; ++tt) {
        int tok = warp * 4 + tt;
        float vals[12];
        float sum = 0.f, sq = 0.f;
#pragma unroll
        for (int k = 0; k < 12; ++k) {
            float v = s[(lane + 32 * k) * 33 + tok];
            vals[k] = v;
            sum += v;
            sq  = fmaf(v, v, sq);
        }
#pragma unroll
        for (int o = 16; o > 0; o >>= 1) {
            sum += __shfl_xor_sync(0xFFFFFFFFu, sum, o);
            sq  += __shfl_xor_sync(0xFFFFFFFFu, sq,  o);
        }
        float mu  = sum * (1.f / (float)EMB);
        float var = sq * (1.f / (float)EMB) - mu * mu;
        float rstd = rsqrtf(var + 1e-5f);

        float* dst = out + ((size_t)b * HW + hw0 + tok) * EMB;
#pragma unroll
        for (int k = 0; k < 12; ++k) {
            int e = lane + 32 * k;
            dst[e] = (vals[k] - mu) * rstd * gamma[e] + beta[e];
        }
    }
}

// ---------------------------------------------------------------------------
// Launcher.
// ---------------------------------------------------------------------------
extern "C" void kernel_launch(void* const* d_in, const int* in_sizes, int n_in,
                              void* d_out, int out_size)
{
    const float* x   = (const float*)d_in[0];
    const float* w3  = (const float*)d_in[1];
    const float* b3  = (const float*)d_in[2];
    const float* w5  = (const float*)d_in[3];
    const float* b5  = (const float*)d_in[4];
    const float* w7  = (const float*)d_in[5];
    const float* b7  = (const float*)d_in[6];
    const float* cw1 = (const float*)d_in[7];
    const float* cw2 = (const float*)d_in[8];
    const float* fw  = (const float*)d_in[9];
    const float* fbi = (const float*)d_in[10];
    const float* lng = (const float*)d_in[11];
    const float* lnb = (const float*)d_in[12];
    float* out = (float*)d_out;

    float* gout;  cudaGetSymbolAddress((void**)&gout,  g_gout);
    float* gavg;  cudaGetSymbolAddress((void**)&gavg,  g_avg);
    float* gmax;  cudaGetSymbolAddress((void**)&gmax,  g_max);
    float* gattn; cudaGetSymbolAddress((void**)&gattn, g_attn);
    __half* xh;  cudaGetSymbolAddress((void**)&xh,  g_xh);
    __half* fh;  cudaGetSymbolAddress((void**)&fh,  g_fh);
    __half* wh3; cudaGetSymbolAddress((void**)&wh3, g_wh3);
    __half* wh5; cudaGetSymbolAddress((void**)&wh5, g_wh5);
    __half* wh7; cudaGetSymbolAddress((void**)&wh7, g_wh7);
    __half* wfh; cudaGetSymbolAddress((void**)&wfh, g_wfh);

    // dynamic smem: 2*(input buf) + 3*(weight buf); epilogue reuses it
    constexpr int SM3 = 2 * (4  * 66 * 32) + 3 * (3 * 128 * 32);   // 53760
    constexpr int SM5 = 2 * (6  * 68 * 32) + 3 * (5 * 128 * 32);   // 87552
    constexpr int SM7 = 2 * (10 * 70 * 32) + 3 * (7 * 64  * 32);   // 87808
    constexpr int LNSM = EMB * 33 * 4;     // 50688
    cudaFuncSetAttribute(conv_f16_kernel<3, 2, 128>, cudaFuncAttributeMaxDynamicSharedMemorySize, SM3);
    cudaFuncSetAttribute(conv_f16_kernel<5, 2, 128>, cudaFuncAttributeMaxDynamicSharedMemorySize, SM5);
    cudaFuncSetAttribute(conv_f16_kernel<7, 4, 64>,  cudaFuncAttributeMaxDynamicSharedMemorySize, SM7);
    cudaFuncSetAttribute(ln_kernel, cudaFuncAttributeMaxDynamicSharedMemorySize, LNSM);

    // pre-pass conversions
    prep_xh_kernel<<<dim3(HW / 128, CB16, BATCH), 256>>>(x, xh);
    prep_wh_kernel<<<(9  * EB * CIN + 255) / 256, 256>>>(w3, wh3, 9);
    prep_wh_kernel<<<(25 * EB * CIN + 255) / 256, 256>>>(w5, wh5, 25);
    prep_wh_kernel<<<(49 * EB * CIN + 255) / 256, 256>>>(w7, wh7, 49);
    prep_wfh_kernel<<<(EMB * EMB + 255) / 256, 256>>>(fw, wfh);

    // convs (split kernels), writing fh fp16 directly
    conv_f16_kernel<3, 2, 128><<<dim3(HH / 2, BATCH, 1), 256, SM3>>>(xh, wh3, b3, fh, 0);
    conv_f16_kernel<5, 2, 128><<<dim3(HH / 2, BATCH, 1), 256, SM5>>>(xh, wh5, b5, fh, EB);
    conv_f16_kernel<7, 4, 64><<<dim3(HH / 4, BATCH, 2), 256, SM7>>>(xh, wh7, b7, fh, 2 * EB);

    pool_kernel<<<dim3(ECB, BATCH), 256>>>(fh, gavg, gmax);
    attn_kernel<<<BATCH, EMB>>>(gavg, gmax, cw1, cw2, gattn);

    gemm_f16_kernel<<<dim3(EMB / 128, HW / 128, BATCH), 256>>>(fh, wfh, gattn, fbi, gout);

    ln_kernel<<<dim3(HW / 32, BATCH), 256, LNSM>>>(gout, lng, lnb, out);
}

// round 13
// speedup vs baseline: 1.0533x; 1.0077x over previous
#include <cuda_runtime.h>
#include <cuda_fp16.h>
#include <cuda_bf16.h>
#include <math.h>

// Problem constants
#define BATCH 32
#define CIN   128
#define CB16  (CIN/16)
#define HH    64
#define WW    64
#define HW    (HH*WW)
#define EMB   384
#define ECB   (EMB/16)     // 24
#define EB    128
#define HID   24

// ---------------- scratch (device globals) ----------------------------------
__device__ float  g_avg  [BATCH * EMB];
__device__ float  g_max  [BATCH * EMB];
__device__ float  g_attn [BATCH * EMB];
__device__ __half g_xh   [(size_t)BATCH * CB16 * HW * 16];  // [b][cb][h][w][c16]
__device__ __half g_fh   [(size_t)BATCH * ECB * HW * 16];   // conv out fp16 [b][cb][hw][c16]
__device__ __half g_wh3  [9  * EB * CIN];                   // [tap][oc][c]
__device__ __half g_wh5  [25 * EB * CIN];
__device__ __half g_wh7  [49 * EB * CIN];
__device__ __half g_wfb  [(size_t)BATCH * EMB * EMB];       // fw*attn fp16 [b][o][c]

// ---- helpers ---------------------------------------------------------------
__device__ __forceinline__ void mma_f16(float& d0, float& d1, float& d2, float& d3,
                                        unsigned a0, unsigned a1, unsigned a2, unsigned a3,
                                        unsigned b0, unsigned b1) {
    asm("mma.sync.aligned.m16n8k16.row.col.f32.f16.f16.f32 "
        "{%0,%1,%2,%3}, {%4,%5,%6,%7}, {%8,%9}, {%0,%1,%2,%3};"
        : "+f"(d0), "+f"(d1), "+f"(d2), "+f"(d3)
        : "r"(a0), "r"(a1), "r"(a2), "r"(a3), "r"(b0), "r"(b1));
}
__device__ __forceinline__ void ldsm_x4(unsigned& r0, unsigned& r1, unsigned& r2, unsigned& r3,
                                        unsigned addr) {
    asm volatile("ldmatrix.sync.aligned.m8n8.x4.shared.b16 {%0,%1,%2,%3}, [%4];"
                 : "=r"(r0), "=r"(r1), "=r"(r2), "=r"(r3) : "r"(addr));
}
__device__ __forceinline__ void cpa16(unsigned dst, const void* src, unsigned srcbytes) {
    asm volatile("cp.async.cg.shared.global [%0], [%1], 16, %2;"
                 :: "r"(dst), "l"(src), "r"(srcbytes) : "memory");
}
__device__ __forceinline__ void cpa_commit() {
    asm volatile("cp.async.commit_group;" ::: "memory");
}
template<int N>
__device__ __forceinline__ void cpa_wait() {
    asm volatile("cp.async.wait_group %0;" :: "n"(N) : "memory");
}

// ---------------------------------------------------------------------------
// Pre-pass: x [B][C][H][W] fp32 -> g_xh [b][cb][h][w][c16] fp16
// ---------------------------------------------------------------------------
__global__ __launch_bounds__(256)
void prep_xh_kernel(const float* __restrict__ x, __half* __restrict__ xh)
{
    __shared__ __half s[16][129];
    const int hw0 = blockIdx.x * 128;
    const int cb  = blockIdx.y;
    const int b   = blockIdx.z;
    const int t   = threadIdx.x;

#pragma unroll
    for (int p = 0; p < 8; ++p) {
        int ci = p * 2 + (t >> 7);
        int j  = t & 127;
        s[ci][j] = __float2half(x[((size_t)(b * CIN + cb * 16 + ci)) * HW + hw0 + j]);
    }
    __syncthreads();

    int j    = t >> 1;
    int csel = t & 1;
    __half tmp[8];
#pragma unroll
    for (int k = 0; k < 8; ++k) tmp[k] = s[csel * 8 + k][j];
    *reinterpret_cast<uint4*>(&xh[(((size_t)(b * CB16 + cb)) * HW + hw0 + j) * 16 + csel * 8]) =
        *reinterpret_cast<uint4*>(tmp);
}

// Pre-pass: w [oc][c][kk] fp32 -> wh [kk][oc][c] fp16
__global__ __launch_bounds__(256)
void prep_wh_kernel(const float* __restrict__ w, __half* __restrict__ wh, int kkN)
{
    int idx = blockIdx.x * 256 + threadIdx.x;
    int total = kkN * EB * CIN;
    if (idx < total) {
        int c  = idx & 127;
        int oc = (idx >> 7) & 127;
        int kk = idx >> 14;
        wh[idx] = __float2half(w[((size_t)oc * CIN + c) * kkN + kk]);
    }
}

// Pre-pass: wfb[b][o][c] = fp16(fw[o][c] * attn[b][c])
__global__ __launch_bounds__(256)
void prep_wfb_kernel(const float* __restrict__ fw, const float* __restrict__ attn,
                     __half* __restrict__ wfb)
{
    size_t idx = (size_t)blockIdx.x * 256 + threadIdx.x;
    if (idx < (size_t)BATCH * EMB * EMB) {
        int c = (int)(idx % EMB);
        int o = (int)((idx / EMB) % EMB);
        int b = (int)(idx / (EMB * EMB));
        wfb[idx] = __float2half(fw[o * EMB + c] * attn[b * EMB + c]);
    }
}

// ---------------------------------------------------------------------------
// Conv via fp16 mma m16n8k16 + ldmatrix + cp.async pipeline; epilogue writes
// fh fp16 [b][cbg][hw][c16] directly (round-12 version).
// ---------------------------------------------------------------------------
template<int K, int ROWS, int OCB>
__global__ __launch_bounds__(256, 2)
void conv_f16_kernel(const __half* __restrict__ xh, const __half* __restrict__ wh,
                     const float* __restrict__ bias, __half* __restrict__ fh, int ch_off)
{
    constexpr int HALO    = K / 2;
    constexpr int WIN     = WW + K - 1;
    constexpr int IN_ROWS = ROWS + K - 1;
    constexpr int NOG     = OCB / 32;
    constexpr int NSG     = 8 / NOG;       // == ROWS
    constexpr int NITEM   = K * OCB;
    constexpr int WCH     = NITEM * 2;
    constexpr int NWPF    = (WCH + 255) / 256;
    constexpr int NCHUNK  = IN_ROWS * WIN * 2;
    constexpr int SINB    = IN_ROWS * WIN * 32;
    constexpr int SWB     = K * OCB * 32;
    constexpr int S       = CB16 * K;

    extern __shared__ __align__(128) unsigned char dsm[];
    const unsigned base = (unsigned)__cvta_generic_to_shared(dsm);
    const unsigned sin_base[2] = { base, base + SINB };
    const unsigned sw_base [3] = { base + 2 * SINB,
                                   base + 2 * SINB + SWB,
                                   base + 2 * SINB + 2 * SWB };

    const int h0     = blockIdx.x * ROWS;
    const int b      = blockIdx.y;
    const int ocbase = blockIdx.z * OCB;
    const int t      = threadIdx.x;
    const int warp   = t >> 5;
    const int lane   = t & 31;
    const int gid    = lane >> 2;
    const int tig    = lane & 3;
    const int ocg    = warp / NSG;
    const int rw     = warp % NSG;

    float d[2][8][4];
#pragma unroll
    for (int mm = 0; mm < 2; ++mm)
#pragma unroll
        for (int n = 0; n < 8; ++n)
#pragma unroll
            for (int j = 0; j < 4; ++j) d[mm][n][j] = 0.f;

    const int laneA  = lane & 15;
    const int cselA  = (lane >> 4) & 1;
    const int laneB4 = (lane & 7) | (((lane >> 4) & 1) << 3);
    const int cselB4 = (lane >> 3) & 1;

    const __half* xbase = xh + ((size_t)(b * CB16)) * HW * 16;

    auto issue_w = [&](int s2) {
        if (s2 >= S) return;
        const int cb2 = s2 / K;
        const int g2  = s2 - cb2 * K;
        const unsigned dstb = sw_base[s2 % 3];
#pragma unroll
        for (int j = 0; j < NWPF; ++j) {
            int q = t + j * 256;
            if (q < WCH) {
                int it = q >> 1, half = q & 1;
                int tap = it / OCB, oc = it - tap * OCB;
                const __half* src = wh + ((size_t)(g2 * K + tap) * EB + ocbase + oc) * CIN
                                       + cb2 * 16 + half * 8;
                unsigned off = (unsigned)(it * 32 + half * 16) ^ ((it & 4) << 2);
                cpa16(dstb + off, src, 16);
            }
        }
    };
    auto issue_in = [&](int cb) {
        const __half* xc = xbase + (size_t)cb * HW * 16;
        const unsigned dstb = sin_base[cb & 1];
        for (int q = t; q < NCHUNK; q += 256) {
            int n = q >> 1, cs = q & 1;
            int r = n / WIN, col = n - r * WIN;
            int gr = h0 + r - HALO, gw = col - HALO;
            bool inb = ((unsigned)gr < HH) && ((unsigned)gw < WW);
            const __half* src = inb ? (xc + ((size_t)gr * WW + gw) * 16 + cs * 8) : xc;
            unsigned off = (unsigned)(n * 32 + cs * 16) ^ ((n & 4) << 2);
            cpa16(dstb + off, src, inb ? 16u : 0u);
        }
    };

    issue_w(0); issue_in(0); cpa_commit();
    issue_w(1); cpa_commit();

    for (int s = 0; s < S; ++s) {
        const int cb = s / K;
        const int g  = s - cb * K;

        cpa_wait<1>();
        __syncthreads();

        issue_w(s + 2);
        if (g == K - 2 && cb + 1 < CB16) issue_in(cb + 1);
        cpa_commit();

        const unsigned swb  = sw_base[s % 3];
        const unsigned sinb = sin_base[cb & 1];
        const int rowbase = (rw + g) * WIN;
#pragma unroll
        for (int kw = 0; kw < K; ++kw) {
            unsigned a[2][4];
#pragma unroll
            for (int mm = 0; mm < 2; ++mm) {
                int gA = kw * OCB + ocg * 32 + mm * 16 + laneA;
                unsigned offA = (unsigned)(gA * 32 + cselA * 16) ^ ((gA & 4) << 2);
                ldsm_x4(a[mm][0], a[mm][1], a[mm][2], a[mm][3], swb + offA);
            }
#pragma unroll
            for (int ntp = 0; ntp < 4; ++ntp) {
                int gB = rowbase + ntp * 16 + laneB4 + kw;
                unsigned offB = (unsigned)(gB * 32 + cselB4 * 16) ^ ((gB & 4) << 2);
                unsigned b0, b1, b2, b3;
                ldsm_x4(b0, b1, b2, b3, sinb + offB);
                const int n0 = ntp * 2;
                mma_f16(d[0][n0][0], d[0][n0][1], d[0][n0][2], d[0][n0][3],
                        a[0][0], a[0][1], a[0][2], a[0][3], b0, b1);
                mma_f16(d[1][n0][0], d[1][n0][1], d[1][n0][2], d[1][n0][3],
                        a[1][0], a[1][1], a[1][2], a[1][3], b0, b1);
                mma_f16(d[0][n0+1][0], d[0][n0+1][1], d[0][n0+1][2], d[0][n0+1][3],
                        a[0][0], a[0][1], a[0][2], a[0][3], b2, b3);
                mma_f16(d[1][n0+1][0], d[1][n0+1][1], d[1][n0+1][2], d[1][n0+1][3],
                        a[1][0], a[1][1], a[1][2], a[1][3], b2, b3);
            }
        }
    }

    // ---- epilogue: smem transpose -> fh fp16 [cbg][hw][c16] ----
    constexpr int P   = ROWS * 64 + 8;
    constexpr int NCH = (OCB / 16) * (ROWS * 64) * 2;
    __syncthreads();
    __half* ep = reinterpret_cast<__half*>(dsm);

    const int hwb = rw * 64;
#pragma unroll
    for (int mm = 0; mm < 2; ++mm) {
        int ocl = ocg * 32 + mm * 16 + gid;
        float bv0 = bias[ocbase + ocl];
        float bv1 = bias[ocbase + ocl + 8];
#pragma unroll
        for (int n = 0; n < 8; ++n) {
            int hwl = hwb + n * 8 + tig * 2;
            *reinterpret_cast<__half2*>(&ep[ocl * P + hwl]) =
                __floats2half2_rn(d[mm][n][0] + bv0, d[mm][n][1] + bv0);
            *reinterpret_cast<__half2*>(&ep[(ocl + 8) * P + hwl]) =
                __floats2half2_rn(d[mm][n][2] + bv1, d[mm][n][3] + bv1);
        }
    }
    __syncthreads();

    const int cbg0 = (ch_off + ocbase) >> 4;
    __half* fdst = fh + ((size_t)b * ECB + cbg0) * HW * 16 + (size_t)h0 * 64 * 16;
#pragma unroll
    for (int qi = 0; qi < NCH / 256; ++qi) {
        int q   = t + qi * 256;
        int cbl = q / (ROWS * 64 * 2);
        int rem = q - cbl * (ROWS * 64 * 2);
        int hwl = rem >> 1;
        int cs  = rem & 1;
        __half tmp[8];
#pragma unroll
        for (int j = 0; j < 8; ++j)
            tmp[j] = ep[(cbl * 16 + cs * 8 + j) * P + hwl];
        *reinterpret_cast<uint4*>(&fdst[((size_t)cbl * HW + hwl) * 16 + cs * 8]) =
            *reinterpret_cast<uint4*>(tmp);
    }
}

// ---------------------------------------------------------------------------
// Pool over fh fp16 [b][cb][hw][c16].
// ---------------------------------------------------------------------------
__global__ __launch_bounds__(256)
void pool_kernel(const __half* __restrict__ fh,
                 float* __restrict__ avg_out, float* __restrict__ max_out)
{
    __shared__ float rs[256][8];
    __shared__ float rm[256][8];

    const int cb = blockIdx.x;
    const int b  = blockIdx.y;
    const int t  = threadIdx.x;
    const int li = t >> 1;
    const int g  = t & 1;

    const __half* src = fh + ((size_t)(b * ECB + cb)) * HW * 16;

    float s[8], m[8];
#pragma unroll
    for (int j = 0; j < 8; ++j) { s[j] = 0.f; m[j] = -INFINITY; }

    for (int it = 0; it < 32; ++it) {
        uint4 v = *reinterpret_cast<const uint4*>(src + ((size_t)(li + it * 128)) * 16 + g * 8);
        const __half2* h2 = reinterpret_cast<const __half2*>(&v);
#pragma unroll
        for (int p = 0; p < 4; ++p) {
            float2 f = __half22float2(h2[p]);
            s[2 * p]     += f.x;
            s[2 * p + 1] += f.y;
            m[2 * p]     = fmaxf(m[2 * p], f.x);
            m[2 * p + 1] = fmaxf(m[2 * p + 1], f.y);
        }
    }
#pragma unroll
    for (int j = 0; j < 8; ++j) { rs[t][j] = s[j]; rm[t][j] = m[j]; }
    __syncthreads();

    for (int o = 64; o > 0; o >>= 1) {
        if (li < o) {
#pragma unroll
            for (int j = 0; j < 8; ++j) {
                rs[t][j] += rs[t + 2 * o][j];
                rm[t][j] = fmaxf(rm[t][j], rm[t + 2 * o][j]);
            }
        }
        __syncthreads();
    }
    if (li == 0) {
#pragma unroll
        for (int j = 0; j < 8; ++j) {
            int e = cb * 16 + g * 8 + j;
            avg_out[b * EMB + e] = rs[t][j] * (1.f / (float)HW);
            max_out[b * EMB + e] = rm[t][j];
        }
    }
}

// ---------------------------------------------------------------------------
// CBAM MLP + sigmoid.
// ---------------------------------------------------------------------------
__global__ __launch_bounds__(EMB)
void attn_kernel(const float* __restrict__ avg_in, const float* __restrict__ max_in,
                 const float* __restrict__ w1, const float* __restrict__ w2,
                 float* __restrict__ attn)
{
    const int b = blockIdx.x;
    const int t = threadIdx.x;

    __shared__ float s_avg[EMB], s_max[EMB];
    __shared__ float s_h[HID];
    __shared__ float s_ha[HID], s_hm[HID];

    s_avg[t] = avg_in[b * EMB + t];
    s_max[t] = max_in[b * EMB + t];
    __syncthreads();

    if (t < HID) {
        float a = 0.f;
        const float* w1r = w1 + t * EMB;
        for (int e = 0; e < EMB; ++e) a = fmaf(s_avg[e], w1r[e], a);
        s_ha[t] = fmaxf(a, 0.f);
    } else if (t >= 32 && t < 32 + HID) {
        int j = t - 32;
        float a = 0.f;
        const float* w1r = w1 + j * EMB;
        for (int e = 0; e < EMB; ++e) a = fmaf(s_max[e], w1r[e], a);
        s_hm[j] = fmaxf(a, 0.f);
    }
    __syncthreads();
    if (t < HID) s_h[t] = s_ha[t] + s_hm[t];
    __syncthreads();

    float v = 0.f;
    const float* w2r = w2 + t * HID;
#pragma unroll
    for (int j = 0; j < HID; ++j) v = fmaf(s_h[j], w2r[j], v);
    attn[b * EMB + t] = 1.f / (1.f + expf(-v));
}

// ---------------------------------------------------------------------------
// Fused 1x1-GEMM + LayerNorm.  Block = 384 oc x 64 hw for one b.
// 8 warps, each 48 oc x 64 hw (3 m-tiles x 8 n-tiles, 96 accum floats).
// cp.async 3-stage pipeline (A: wfb[b] 384x16/step, B: fh 64x16/step).
// Epilogue: two half-passes of 32 tokens through smem [32][392] fp32,
// per-token mean/var (fp32), gamma/beta, write DIRECTLY to d_out [b][hw][E].
// ---------------------------------------------------------------------------
#define PS 392
__global__ __launch_bounds__(256)
void gemm_ln_kernel(const __half* __restrict__ fh, const __half* __restrict__ wfb,
                    const float* __restrict__ fb,
                    const float* __restrict__ gamma, const float* __restrict__ beta,
                    float* __restrict__ out)
{
    extern __shared__ __align__(128) unsigned char dsm[];
    const unsigned base = (unsigned)__cvta_generic_to_shared(dsm);
    const unsigned sA[3] = { base, base + 12288, base + 24576 };
    const unsigned sB[3] = { base + 36864, base + 36864 + 2048, base + 36864 + 4096 };

    const int hw0 = blockIdx.x * 64;
    const int b   = blockIdx.y;
    const int t   = threadIdx.x;
    const int warp = t >> 5;
    const int lane = t & 31;
    const int gid  = lane >> 2;
    const int tig  = lane & 3;

    const int laneA  = lane & 15;
    const int cselA  = (lane >> 4) & 1;
    const int laneB4 = (lane & 7) | (((lane >> 4) & 1) << 3);
    const int cselB4 = (lane >> 3) & 1;

    float d[3][8][4];
#pragma unroll
    for (int mm = 0; mm < 3; ++mm)
#pragma unroll
        for (int n = 0; n < 8; ++n)
#pragma unroll
            for (int j = 0; j < 4; ++j) d[mm][n][j] = 0.f;

    const __half* Abase = wfb + (size_t)b * EMB * EMB;
    const __half* Bbase = fh + ((size_t)b * ECB) * HW * 16 + (size_t)hw0 * 16;

    // staging: A = 768 16B-chunks (3/thread), B = 128 chunks (t<128)
    auto issue = [&](int s2) {
        if (s2 >= ECB) return;
        const unsigned dA = sA[s2 % 3];
        const unsigned dB = sB[s2 % 3];
#pragma unroll
        for (int j = 0; j < 3; ++j) {
            int q = t + j * 256;
            int row = q >> 1, cs = q & 1;
            unsigned off = (unsigned)(row * 32 + cs * 16) ^ ((row & 4) << 2);
            cpa16(dA + off, Abase + (size_t)row * EMB + s2 * 16 + cs * 8, 16);
        }
        if (t < 128) {
            int row = t >> 1, cs = t & 1;
            unsigned off = (unsigned)(row * 32 + cs * 16) ^ ((row & 4) << 2);
            cpa16(dB + off, Bbase + (size_t)s2 * HW * 16 + row * 16 + cs * 8, 16);
        }
    };

    issue(0); cpa_commit();
    issue(1); cpa_commit();

    for (int cb = 0; cb < ECB; ++cb) {
        cpa_wait<1>();
        __syncthreads();
        issue(cb + 2);
        cpa_commit();

        const unsigned pA = sA[cb % 3];
        const unsigned pB = sB[cb % 3];
        unsigned a[3][4];
#pragma unroll
        for (int mm = 0; mm < 3; ++mm) {
            int gA = warp * 48 + mm * 16 + laneA;
            unsigned offA = (unsigned)(gA * 32 + cselA * 16) ^ ((gA & 4) << 2);
            ldsm_x4(a[mm][0], a[mm][1], a[mm][2], a[mm][3], pA + offA);
        }
#pragma unroll
        for (int ntp = 0; ntp < 4; ++ntp) {
            int gB = ntp * 16 + laneB4;
            unsigned offB = (unsigned)(gB * 32 + cselB4 * 16) ^ ((gB & 4) << 2);
            unsigned b0, b1, b2, b3;
            ldsm_x4(b0, b1, b2, b3, pB + offB);
            const int n0 = ntp * 2;
#pragma unroll
            for (int mm = 0; mm < 3; ++mm) {
                mma_f16(d[mm][n0][0], d[mm][n0][1], d[mm][n0][2], d[mm][n0][3],
                        a[mm][0], a[mm][1], a[mm][2], a[mm][3], b0, b1);
                mma_f16(d[mm][n0+1][0], d[mm][n0+1][1], d[mm][n0+1][2], d[mm][n0+1][3],
                        a[mm][0], a[mm][1], a[mm][2], a[mm][3], b2, b3);
            }
        }
    }

    // ---- fused LayerNorm epilogue ----
    __syncthreads();
    float* ep = reinterpret_cast<float*>(dsm);   // [32 tokens][PS]

#pragma unroll
    for (int half = 0; half < 2; ++half) {
        // write phase: this half's 32 tokens
#pragma unroll
        for (int mm = 0; mm < 3; ++mm) {
            int oc0 = warp * 48 + mm * 16 + gid;
            float bv0 = fb[oc0];
            float bv1 = fb[oc0 + 8];
#pragma unroll
            for (int nn = 0; nn < 4; ++nn) {
                int nt   = half * 4 + nn;
                int tokl = nn * 8 + tig * 2;
                ep[tokl * PS + oc0]           = d[mm][nt][0] + bv0;
                ep[(tokl + 1) * PS + oc0]     = d[mm][nt][1] + bv0;
                ep[tokl * PS + oc0 + 8]       = d[mm][nt][2] + bv1;
                ep[(tokl + 1) * PS + oc0 + 8] = d[mm][nt][3] + bv1;
            }
        }
        __syncthreads();

        // LN phase: warp handles 4 tokens
#pragma unroll
        for (int tt = 0; tt < 4; ++tt) {
            int tok = warp * 4 + tt;
            float vals[12];
            float sum = 0.f, sq = 0.f;
#pragma unroll
            for (int k = 0; k < 12; ++k) {
                float v = ep[tok * PS + lane + 32 * k];
                vals[k] = v;
                sum += v;
                sq  = fmaf(v, v, sq);
            }
#pragma unroll
            for (int o = 16; o > 0; o >>= 1) {
                sum += __shfl_xor_sync(0xFFFFFFFFu, sum, o);
                sq  += __shfl_xor_sync(0xFFFFFFFFu, sq,  o);
            }
            float mu  = sum * (1.f / (float)EMB);
            float var = sq * (1.f / (float)EMB) - mu * mu;
            float rstd = rsqrtf(var + 1e-5f);

            float* dst = out + ((size_t)b * HW + hw0 + half * 32 + tok) * EMB;
#pragma unroll
            for (int k = 0; k < 12; ++k) {
                int e = lane + 32 * k;
                dst[e] = (vals[k] - mu) * rstd * gamma[e] + beta[e];
            }
        }
        __syncthreads();   // before next half overwrites ep
    }
}

// ---------------------------------------------------------------------------
// Launcher.
// ---------------------------------------------------------------------------
extern "C" void kernel_launch(void* const* d_in, const int* in_sizes, int n_in,
                              void* d_out, int out_size)
{
    const float* x   = (const float*)d_in[0];
    const float* w3  = (const float*)d_in[1];
    const float* b3  = (const float*)d_in[2];
    const float* w5  = (const float*)d_in[3];
    const float* b5  = (const float*)d_in[4];
    const float* w7  = (const float*)d_in[5];
    const float* b7  = (const float*)d_in[6];
    const float* cw1 = (const float*)d_in[7];
    const float* cw2 = (const float*)d_in[8];
    const float* fw  = (const float*)d_in[9];
    const float* fbi = (const float*)d_in[10];
    const float* lng = (const float*)d_in[11];
    const float* lnb = (const float*)d_in[12];
    float* out = (float*)d_out;

    float* gavg;  cudaGetSymbolAddress((void**)&gavg,  g_avg);
    float* gmax;  cudaGetSymbolAddress((void**)&gmax,  g_max);
    float* gattn; cudaGetSymbolAddress((void**)&gattn, g_attn);
    __half* xh;  cudaGetSymbolAddress((void**)&xh,  g_xh);
    __half* fh;  cudaGetSymbolAddress((void**)&fh,  g_fh);
    __half* wh3; cudaGetSymbolAddress((void**)&wh3, g_wh3);
    __half* wh5; cudaGetSymbolAddress((void**)&wh5, g_wh5);
    __half* wh7; cudaGetSymbolAddress((void**)&wh7, g_wh7);
    __half* wfb; cudaGetSymbolAddress((void**)&wfb, g_wfb);

    constexpr int SM3 = 2 * (4  * 66 * 32) + 3 * (3 * 128 * 32);   // 53760
    constexpr int SM5 = 2 * (6  * 68 * 32) + 3 * (5 * 128 * 32);   // 87552
    constexpr int SM7 = 2 * (10 * 70 * 32) + 3 * (7 * 64  * 32);   // 87808
    constexpr int GLSM = 32 * PS * 4;                              // 50176 (> 43008 staging)
    cudaFuncSetAttribute(conv_f16_kernel<3, 2, 128>, cudaFuncAttributeMaxDynamicSharedMemorySize, SM3);
    cudaFuncSetAttribute(conv_f16_kernel<5, 2, 128>, cudaFuncAttributeMaxDynamicSharedMemorySize, SM5);
    cudaFuncSetAttribute(conv_f16_kernel<7, 4, 64>,  cudaFuncAttributeMaxDynamicSharedMemorySize, SM7);
    cudaFuncSetAttribute(gemm_ln_kernel, cudaFuncAttributeMaxDynamicSharedMemorySize, GLSM);

    // pre-pass conversions
    prep_xh_kernel<<<dim3(HW / 128, CB16, BATCH), 256>>>(x, xh);
    prep_wh_kernel<<<(9  * EB * CIN + 255) / 256, 256>>>(w3, wh3, 9);
    prep_wh_kernel<<<(25 * EB * CIN + 255) / 256, 256>>>(w5, wh5, 25);
    prep_wh_kernel<<<(49 * EB * CIN + 255) / 256, 256>>>(w7, wh7, 49);

    // convs, writing fh fp16 directly
    conv_f16_kernel<3, 2, 128><<<dim3(HH / 2, BATCH, 1), 256, SM3>>>(xh, wh3, b3, fh, 0);
    conv_f16_kernel<5, 2, 128><<<dim3(HH / 2, BATCH, 1), 256, SM5>>>(xh, wh5, b5, fh, EB);
    conv_f16_kernel<7, 4, 64><<<dim3(HH / 4, BATCH, 2), 256, SM7>>>(xh, wh7, b7, fh, 2 * EB);

    pool_kernel<<<dim3(ECB, BATCH), 256>>>(fh, gavg, gmax);
    attn_kernel<<<BATCH, EMB>>>(gavg, gmax, cw1, cw2, gattn);

    // per-batch attn-scaled fusion weights
    {
        size_t total = (size_t)BATCH * EMB * EMB;
        prep_wfb_kernel<<<(unsigned)((total + 255) / 256), 256>>>(fw, gattn, wfb);
    }

    // fused GEMM + LayerNorm -> d_out
    gemm_ln_kernel<<<dim3(HW / 64, BATCH), 256, GLSM>>>(fh, wfb, fbi, lng, lnb, out);
}